// round 7
// baseline (speedup 1.0000x reference)
#include <cuda_runtime.h>
#include <cuda_bf16.h>

// Flash attention via mma.sync (bf16x3 split precision), pipelined K/V loads.
// B=32, S=2048, D=128. Grid (16, 32), 256 threads = 8 warps, warp m-tile = 16.

// scale = log2(e)/sqrt(128): softmax uses ex2 directly.
#define SCALE_LOG2E 0.12754949506278886f

// ---- SMEM layout (bytes). All tiles use 256B rows with XOR-16B-unit swizzle.
#define SM_QH 0           // Q hi  [128 rows][128 bf16]
#define SM_QL 32768       // Q lo
#define SM_KH 65536       // K hi, 2 bufs x [64][128] bf16 (16384 each)
#define SM_KL 98304       // K lo, 2 bufs
#define SM_VH 131072      // V hi, 2 bufs ([key][d] layout)
#define SM_VL 163840      // V lo, 2 bufs
#define SM_TOTAL 196608

#define LDSMX4(R, A) \
    asm volatile("ldmatrix.sync.aligned.m8n8.x4.shared.b16 {%0,%1,%2,%3}, [%4];" \
        : "=r"((R)[0]), "=r"((R)[1]), "=r"((R)[2]), "=r"((R)[3]) : "r"(A))

#define LDSMX4T(R, A) \
    asm volatile("ldmatrix.sync.aligned.m8n8.x4.trans.shared.b16 {%0,%1,%2,%3}, [%4];" \
        : "=r"((R)[0]), "=r"((R)[1]), "=r"((R)[2]), "=r"((R)[3]) : "r"(A))

__device__ __forceinline__ void mma16816(float* d, const unsigned* a, const unsigned* b) {
    asm volatile(
        "mma.sync.aligned.m16n8k16.row.col.f32.bf16.bf16.f32 "
        "{%0,%1,%2,%3}, {%4,%5,%6,%7}, {%8,%9}, {%0,%1,%2,%3};"
        : "+f"(d[0]), "+f"(d[1]), "+f"(d[2]), "+f"(d[3])
        : "r"(a[0]), "r"(a[1]), "r"(a[2]), "r"(a[3]), "r"(b[0]), "r"(b[1]));
}

__device__ __forceinline__ float ex2f(float x) {
    float r;
    asm("ex2.approx.f32 %0, %1;" : "=f"(r) : "f"(x));
    return r;
}

__device__ __forceinline__ unsigned smem_u32(const void* p) {
    unsigned a;
    asm("{ .reg .u64 t; cvta.to.shared.u64 t, %1; cvt.u32.u64 %0, t; }"
        : "=r"(a) : "l"(p));
    return a;
}

__device__ __forceinline__ unsigned pack2(__nv_bfloat16 a, __nv_bfloat16 b) {
    return (unsigned)__bfloat16_as_ushort(a) | ((unsigned)__bfloat16_as_ushort(b) << 16);
}

// swizzled byte offset inside a [rows][128 bf16] tile (256B rows, 16B units
// XORed with row&7) for 4 consecutive bf16 at column c4 (multiple of 4).
__device__ __forceinline__ unsigned sw_off(int row, int c4) {
    unsigned u = (unsigned)c4 >> 3;
    return (unsigned)row * 256u + (((u ^ ((unsigned)row & 7u)) << 4)) +
           (((unsigned)c4 & 4u) << 1);
}

__device__ __forceinline__ void split_store(char* hb, char* lb, unsigned off, float4 x) {
    __nv_bfloat16 h0 = __float2bfloat16_rn(x.x);
    __nv_bfloat16 h1 = __float2bfloat16_rn(x.y);
    __nv_bfloat16 h2 = __float2bfloat16_rn(x.z);
    __nv_bfloat16 h3 = __float2bfloat16_rn(x.w);
    __nv_bfloat16 l0 = __float2bfloat16_rn(x.x - __bfloat162float(h0));
    __nv_bfloat16 l1 = __float2bfloat16_rn(x.y - __bfloat162float(h1));
    __nv_bfloat16 l2 = __float2bfloat16_rn(x.z - __bfloat162float(h2));
    __nv_bfloat16 l3 = __float2bfloat16_rn(x.w - __bfloat162float(h3));
    *(uint2*)(hb + off) = make_uint2(pack2(h0, h1), pack2(h2, h3));
    *(uint2*)(lb + off) = make_uint2(pack2(l0, l1), pack2(l2, l3));
}

// Batched 8x LDG.128 of one 64x128 fp32 tile slice for this thread.
__device__ __forceinline__ void ldg8(const float* base, int tid, float4* r) {
    #pragma unroll
    for (int j = 0; j < 8; j++) {
        int lin = j * 256 + tid;
        int row = lin >> 5;
        int c4  = (lin & 31) << 2;
        r[j] = *(const float4*)(base + row * 128 + c4);
    }
}

__device__ __forceinline__ void sts8(char* hb, char* lb, int tid, const float4* r) {
    #pragma unroll
    for (int j = 0; j < 8; j++) {
        int lin = j * 256 + tid;
        int row = lin >> 5;
        int c4  = (lin & 31) << 2;
        split_store(hb, lb, sw_off(row, c4), r[j]);
    }
}

__global__ void __launch_bounds__(256, 1)
fa_mma_kernel(const float* __restrict__ q, const float* __restrict__ k,
              const float* __restrict__ v, float* __restrict__ out)
{
    extern __shared__ __align__(1024) char smem[];
    const unsigned sb = smem_u32(smem);
    const int tid  = threadIdx.x;
    const int wid  = tid >> 5;
    const int lane = tid & 31;
    const int b    = blockIdx.y;
    const int m0   = blockIdx.x * 128;
    const int wm   = wid * 16;

    // lane decompositions for ldmatrix addressing
    const int lrowA = lane & 15;
    const unsigned xA = (unsigned)(lrowA & 7);
    const int lnB  = ((lane >> 4) << 3) + (lane & 7);
    const unsigned uAadd = (unsigned)(lane >> 4);
    const unsigned uBadd = (unsigned)((lane & 8) >> 3);

    // ---- Q load: scale (incl. log2e), split, store ----
    const float* qb = q + ((size_t)b * 2048 + m0) * 128;
    {
        char* QH = smem + SM_QH;
        char* QL = smem + SM_QL;
        #pragma unroll
        for (int j = 0; j < 16; j++) {
            int lin = j * 256 + tid;
            int row = lin >> 5;
            int c4  = (lin & 31) << 2;
            float4 x = *(const float4*)(qb + row * 128 + c4);
            x.x *= SCALE_LOG2E; x.y *= SCALE_LOG2E;
            x.z *= SCALE_LOG2E; x.w *= SCALE_LOG2E;
            split_store(QH, QL, sw_off(row, c4), x);
        }
    }

    const float* kbase = k + (size_t)b * 2048 * 128;
    const float* vbase = v + (size_t)b * 2048 * 128;
    // prologue: tile 0 into buf 0
    {
        float4 r[8];
        ldg8(kbase, tid, r);
        sts8(smem + SM_KH, smem + SM_KL, tid, r);
        ldg8(vbase, tid, r);
        sts8(smem + SM_VH, smem + SM_VL, tid, r);
    }
    __syncthreads();

    float O[16][4];
    #pragma unroll
    for (int i = 0; i < 16; i++)
        #pragma unroll
        for (int j = 0; j < 4; j++) O[i][j] = 0.0f;
    float lsum0 = 0.0f, lsum1 = 0.0f;

    const unsigned qaH = sb + SM_QH + (unsigned)(wm + lrowA) * 256;
    const unsigned qaL = qaH + 32768;

    for (int t = 0; t < 32; t++) {
        const int buf = t & 1;
        const int nbuf = buf ^ 1;

        // ---- issue K(t+1) loads (batched; consumed after GEMM1) ----
        float4 kpre[8];
        if (t < 31) ldg8(kbase + (size_t)(t + 1) * 8192, tid, kpre);

        // ---- GEMM1: S = Qh.Kh + Ql.Kh + Qh.Kl ----
        float S[8][4];
        #pragma unroll
        for (int nt = 0; nt < 8; nt++)
            #pragma unroll
            for (int j = 0; j < 4; j++) S[nt][j] = 0.0f;

        const unsigned khb = sb + SM_KH + buf * 16384 + (unsigned)lnB * 256;
        const unsigned klb = khb + 32768;

        #pragma unroll
        for (int ks = 0; ks < 8; ks++) {
            unsigned aH[4], aL[4], bb[16];
            unsigned aofs = (((unsigned)(2 * ks) + uAadd) ^ xA) << 4;
            LDSMX4(aH, qaH + aofs);
            LDSMX4(aL, qaL + aofs);
            unsigned bofs = (((unsigned)(2 * ks) + uBadd) ^ xA) << 4;
            #pragma unroll
            for (int np = 0; np < 4; np++) LDSMX4(&bb[np * 4], khb + np * 4096 + bofs);
            #pragma unroll
            for (int nt = 0; nt < 8; nt++) mma16816(S[nt], aH, &bb[nt * 2]);
            #pragma unroll
            for (int nt = 0; nt < 8; nt++) mma16816(S[nt], aL, &bb[nt * 2]);
            #pragma unroll
            for (int np = 0; np < 4; np++) LDSMX4(&bb[np * 4], klb + np * 4096 + bofs);
            #pragma unroll
            for (int nt = 0; nt < 8; nt++) mma16816(S[nt], aH, &bb[nt * 2]);
        }

        // ---- store K(t+1): loads have had a full GEMM to land ----
        if (t < 31)
            sts8(smem + SM_KH + nbuf * 16384, smem + SM_KL + nbuf * 16384, tid, kpre);

        // ---- softmax: p = 2^s (log2e folded into Q scale) ----
        unsigned Ph[16], Pl[16];
        #pragma unroll
        for (int nt = 0; nt < 8; nt++) {
            float p0 = ex2f(S[nt][0]);
            float p1 = ex2f(S[nt][1]);
            float p2 = ex2f(S[nt][2]);
            float p3 = ex2f(S[nt][3]);
            lsum0 += p0 + p1;
            lsum1 += p2 + p3;
            __nv_bfloat16 h0 = __float2bfloat16_rn(p0);
            __nv_bfloat16 h1 = __float2bfloat16_rn(p1);
            __nv_bfloat16 h2 = __float2bfloat16_rn(p2);
            __nv_bfloat16 h3 = __float2bfloat16_rn(p3);
            Ph[nt * 2]     = pack2(h0, h1);
            Ph[nt * 2 + 1] = pack2(h2, h3);
            Pl[nt * 2]     = pack2(__float2bfloat16_rn(p0 - __bfloat162float(h0)),
                                   __float2bfloat16_rn(p1 - __bfloat162float(h1)));
            Pl[nt * 2 + 1] = pack2(__float2bfloat16_rn(p2 - __bfloat162float(h2)),
                                   __float2bfloat16_rn(p3 - __bfloat162float(h3)));
        }

        // ---- issue V(t+1) loads (consumed after GEMM2) ----
        float4 vpre[8];
        if (t < 31) ldg8(vbase + (size_t)(t + 1) * 8192, tid, vpre);

        // ---- GEMM2: O += Ph.Vh + Pl.Vh + Ph.Vl ----
        const unsigned vhb = sb + SM_VH + buf * 16384 + (unsigned)lrowA * 256;
        const unsigned vlb = vhb + 32768;
        #pragma unroll
        for (int ks2 = 0; ks2 < 4; ks2++) {
            const unsigned* Ah = &Ph[ks2 * 4];
            const unsigned* Al = &Pl[ks2 * 4];
            #pragma unroll
            for (int g = 0; g < 2; g++) {
                unsigned bb[16];
                #pragma unroll
                for (int np = 0; np < 4; np++) {
                    unsigned u = (unsigned)(g * 8 + np * 2) + uAadd;
                    LDSMX4T(&bb[np * 4], vhb + ks2 * 4096 + ((u ^ xA) << 4));
                }
                #pragma unroll
                for (int nt = 0; nt < 8; nt++) mma16816(O[g * 8 + nt], Ah, &bb[nt * 2]);
                #pragma unroll
                for (int nt = 0; nt < 8; nt++) mma16816(O[g * 8 + nt], Al, &bb[nt * 2]);
                #pragma unroll
                for (int np = 0; np < 4; np++) {
                    unsigned u = (unsigned)(g * 8 + np * 2) + uAadd;
                    LDSMX4T(&bb[np * 4], vlb + ks2 * 4096 + ((u ^ xA) << 4));
                }
                #pragma unroll
                for (int nt = 0; nt < 8; nt++) mma16816(O[g * 8 + nt], Ah, &bb[nt * 2]);
            }
        }

        // ---- store V(t+1) ----
        if (t < 31)
            sts8(smem + SM_VH + nbuf * 16384, smem + SM_VL + nbuf * 16384, tid, vpre);

        __syncthreads();
    }

    // ---- epilogue ----
    lsum0 += __shfl_xor_sync(0xffffffffu, lsum0, 1);
    lsum0 += __shfl_xor_sync(0xffffffffu, lsum0, 2);
    lsum1 += __shfl_xor_sync(0xffffffffu, lsum1, 1);
    lsum1 += __shfl_xor_sync(0xffffffffu, lsum1, 2);
    const float inv0 = 1.0f / lsum0;
    const float inv1 = 1.0f / lsum1;

    const int r0 = m0 + wm + (lane >> 2);
    float* ob = out + ((size_t)b * 2048 + r0) * 128;
    #pragma unroll
    for (int nt = 0; nt < 16; nt++) {
        int col = nt * 8 + (lane & 3) * 2;
        *(float2*)(ob + col) = make_float2(O[nt][0] * inv0, O[nt][1] * inv0);
        *(float2*)(ob + 8 * 128 + col) = make_float2(O[nt][2] * inv1, O[nt][3] * inv1);
    }
}

extern "C" void kernel_launch(void* const* d_in, const int* in_sizes, int n_in,
                              void* d_out, int out_size)
{
    const float* q = (const float*)d_in[0];
    const float* k = (const float*)d_in[1];
    const float* v = (const float*)d_in[2];
    float* out = (float*)d_out;

    cudaFuncSetAttribute(fa_mma_kernel,
                         cudaFuncAttributeMaxDynamicSharedMemorySize, SM_TOTAL);

    dim3 grid(16, 32);
    fa_mma_kernel<<<grid, 256, SM_TOTAL>>>(q, k, v, out);
}

// round 8
// speedup vs baseline: 1.0284x; 1.0284x over previous
#include <cuda_runtime.h>
#include <cuda_bf16.h>

// Flash attention via mma.sync, bf16x3 split precision.
// BM=64 per CTA, 2 CTAs/SM for latency hiding. Grid (32, 32), 256 threads.
// Warp (m = wid&3, nh = wid>>2): rows m*16..+16, key/col half nh.

// exact: log2(e) / sqrt(128), folded at compile time
#define SCALE_LOG2E (1.4426950408889634f * 0.08838834764831845f)

// ---- SMEM layout per CTA (bytes) ----
#define SM_QH 0           // Q hi [64][128] bf16 (256B rows, swizzled)
#define SM_QL 16384
#define SM_KH 32768       // K hi [64][128]
#define SM_KL 49152
#define SM_VH 65536       // V hi [64 keys][128 d]
#define SM_VL 81920
#define SM_PH 98304       // P hi [64 q-rows][64 k-cols] bf16 (128B rows)
#define SM_PL 106496
#define SM_TOTAL 114688   // 112 KB -> 2 CTAs/SM

#define LDSMX4(R, A) \
    asm volatile("ldmatrix.sync.aligned.m8n8.x4.shared.b16 {%0,%1,%2,%3}, [%4];" \
        : "=r"((R)[0]), "=r"((R)[1]), "=r"((R)[2]), "=r"((R)[3]) : "r"(A))

#define LDSMX4T(R, A) \
    asm volatile("ldmatrix.sync.aligned.m8n8.x4.trans.shared.b16 {%0,%1,%2,%3}, [%4];" \
        : "=r"((R)[0]), "=r"((R)[1]), "=r"((R)[2]), "=r"((R)[3]) : "r"(A))

__device__ __forceinline__ void mma16816(float* d, const unsigned* a, const unsigned* b) {
    asm volatile(
        "mma.sync.aligned.m16n8k16.row.col.f32.bf16.bf16.f32 "
        "{%0,%1,%2,%3}, {%4,%5,%6,%7}, {%8,%9}, {%0,%1,%2,%3};"
        : "+f"(d[0]), "+f"(d[1]), "+f"(d[2]), "+f"(d[3])
        : "r"(a[0]), "r"(a[1]), "r"(a[2]), "r"(a[3]), "r"(b[0]), "r"(b[1]));
}

__device__ __forceinline__ float ex2f(float x) {
    float r;
    asm("ex2.approx.f32 %0, %1;" : "=f"(r) : "f"(x));
    return r;
}

__device__ __forceinline__ unsigned smem_u32(const void* p) {
    unsigned a;
    asm("{ .reg .u64 t; cvta.to.shared.u64 t, %1; cvt.u32.u64 %0, t; }"
        : "=r"(a) : "l"(p));
    return a;
}

__device__ __forceinline__ unsigned pack2(__nv_bfloat16 a, __nv_bfloat16 b) {
    return (unsigned)__bfloat16_as_ushort(a) | ((unsigned)__bfloat16_as_ushort(b) << 16);
}

// swizzled byte offset in a [rows][128 bf16] tile (256B rows, 16B units XOR row&7)
__device__ __forceinline__ unsigned sw_off(int row, int c4) {
    unsigned u = (unsigned)c4 >> 3;
    return (unsigned)row * 256u + ((u ^ ((unsigned)row & 7u)) << 4) +
           (((unsigned)c4 & 4u) << 1);
}

// swizzled byte offset in a [rows][64 bf16] tile (128B rows), col even
__device__ __forceinline__ unsigned sw_off_p(int row, int c) {
    unsigned u = (unsigned)c >> 3;
    return (unsigned)row * 128u + ((u ^ ((unsigned)row & 7u)) << 4) +
           ((unsigned)c & 7u) * 2u;
}

__device__ __forceinline__ void split_store(char* hb, char* lb, unsigned off, float4 x) {
    __nv_bfloat16 h0 = __float2bfloat16_rn(x.x);
    __nv_bfloat16 h1 = __float2bfloat16_rn(x.y);
    __nv_bfloat16 h2 = __float2bfloat16_rn(x.z);
    __nv_bfloat16 h3 = __float2bfloat16_rn(x.w);
    __nv_bfloat16 l0 = __float2bfloat16_rn(x.x - __bfloat162float(h0));
    __nv_bfloat16 l1 = __float2bfloat16_rn(x.y - __bfloat162float(h1));
    __nv_bfloat16 l2 = __float2bfloat16_rn(x.z - __bfloat162float(h2));
    __nv_bfloat16 l3 = __float2bfloat16_rn(x.w - __bfloat162float(h3));
    *(uint2*)(hb + off) = make_uint2(pack2(h0, h1), pack2(h2, h3));
    *(uint2*)(lb + off) = make_uint2(pack2(l0, l1), pack2(l2, l3));
}

// one 64x128 fp32 tile: 2048 float4, 8 per thread
__device__ __forceinline__ void ldg8(const float* base, int tid, float4* r) {
    #pragma unroll
    for (int j = 0; j < 8; j++) {
        int lin = j * 256 + tid;
        int row = lin >> 5;
        int c4  = (lin & 31) << 2;
        r[j] = *(const float4*)(base + row * 128 + c4);
    }
}

__device__ __forceinline__ void sts8(char* hb, char* lb, int tid, const float4* r) {
    #pragma unroll
    for (int j = 0; j < 8; j++) {
        int lin = j * 256 + tid;
        int row = lin >> 5;
        int c4  = (lin & 31) << 2;
        split_store(hb, lb, sw_off(row, c4), r[j]);
    }
}

__global__ void __launch_bounds__(256, 2)
fa_mma2_kernel(const float* __restrict__ q, const float* __restrict__ k,
               const float* __restrict__ v, float* __restrict__ out)
{
    extern __shared__ __align__(1024) char smem[];
    const unsigned sb = smem_u32(smem);
    const int tid  = threadIdx.x;
    const int wid  = tid >> 5;
    const int lane = tid & 31;
    const int b    = blockIdx.y;
    const int m0   = blockIdx.x * 64;
    const int m    = wid & 3;
    const int nh   = wid >> 2;
    const int wm   = m * 16;

    const int lrowA = lane & 15;
    const unsigned xA = (unsigned)(lane & 7);
    const int lnB  = nh * 32 + ((lane >> 4) << 3) + (lane & 7);
    const unsigned uAadd = (unsigned)(lane >> 4);
    const unsigned uBadd = (unsigned)((lane & 8) >> 3);

    // ---- Q load: scale (incl. log2e), split, store ----
    const float* qb = q + ((size_t)b * 2048 + m0) * 128;
    {
        char* QH = smem + SM_QH;
        char* QL = smem + SM_QL;
        #pragma unroll
        for (int j = 0; j < 8; j++) {
            int lin = j * 256 + tid;
            int row = lin >> 5;
            int c4  = (lin & 31) << 2;
            float4 x = *(const float4*)(qb + row * 128 + c4);
            x.x *= SCALE_LOG2E; x.y *= SCALE_LOG2E;
            x.z *= SCALE_LOG2E; x.w *= SCALE_LOG2E;
            split_store(QH, QL, sw_off(row, c4), x);
        }
    }

    const float* kbase = k + (size_t)b * 2048 * 128;
    const float* vbase = v + (size_t)b * 2048 * 128;

    float O[8][4];
    #pragma unroll
    for (int i = 0; i < 8; i++)
        #pragma unroll
        for (int j = 0; j < 4; j++) O[i][j] = 0.0f;
    float lsum0 = 0.0f, lsum1 = 0.0f;

    const unsigned qaH = sb + SM_QH + (unsigned)(wm + lrowA) * 256;
    const unsigned qaL = qaH + 16384;
    const unsigned khb = sb + SM_KH + (unsigned)lnB * 256;
    const unsigned klb = khb + 16384;
    const unsigned vhb = sb + SM_VH + (unsigned)lrowA * 256;
    const unsigned vlb = vhb + 16384;
    const unsigned paH = sb + SM_PH + (unsigned)(wm + lrowA) * 128;
    const unsigned paL = paH + 8192;

    for (int t = 0; t < 32; t++) {
        __syncthreads();   // tile t-1 and P fully consumed
        {
            float4 rk[8], rv[8];
            ldg8(kbase + (size_t)t * 8192, tid, rk);
            ldg8(vbase + (size_t)t * 8192, tid, rv);
            sts8(smem + SM_KH, smem + SM_KL, tid, rk);
            sts8(smem + SM_VH, smem + SM_VL, tid, rv);
        }
        __syncthreads();

        // ---- GEMM1: S[16 x 32] = Qh.Kh + Ql.Kh + Qh.Kl ----
        float S[4][4];
        #pragma unroll
        for (int nt = 0; nt < 4; nt++)
            #pragma unroll
            for (int j = 0; j < 4; j++) S[nt][j] = 0.0f;

        #pragma unroll
        for (int ks = 0; ks < 8; ks++) {
            unsigned aH[4], aL[4], bb[8];
            unsigned aofs = (((unsigned)(2 * ks) + uAadd) ^ xA) << 4;
            LDSMX4(aH, qaH + aofs);
            LDSMX4(aL, qaL + aofs);
            unsigned bofs = (((unsigned)(2 * ks) + uBadd) ^ xA) << 4;
            LDSMX4(&bb[0], khb + bofs);
            LDSMX4(&bb[4], khb + 4096 + bofs);
            #pragma unroll
            for (int nt = 0; nt < 4; nt++) mma16816(S[nt], aH, &bb[nt * 2]);
            #pragma unroll
            for (int nt = 0; nt < 4; nt++) mma16816(S[nt], aL, &bb[nt * 2]);
            LDSMX4(&bb[0], klb + bofs);
            LDSMX4(&bb[4], klb + 4096 + bofs);
            #pragma unroll
            for (int nt = 0; nt < 4; nt++) mma16816(S[nt], aH, &bb[nt * 2]);
        }

        // ---- softmax: p = 2^s; split; stage P into SMEM ----
        {
            const int r0 = wm + (lane >> 2);
            const int r1 = r0 + 8;
            const int cb = nh * 32 + (lane & 3) * 2;
            #pragma unroll
            for (int nt = 0; nt < 4; nt++) {
                float p0 = ex2f(S[nt][0]);
                float p1 = ex2f(S[nt][1]);
                float p2 = ex2f(S[nt][2]);
                float p3 = ex2f(S[nt][3]);
                lsum0 += p0 + p1;
                lsum1 += p2 + p3;
                int c = cb + nt * 8;
                __nv_bfloat16 h0 = __float2bfloat16_rn(p0);
                __nv_bfloat16 h1 = __float2bfloat16_rn(p1);
                __nv_bfloat16 h2 = __float2bfloat16_rn(p2);
                __nv_bfloat16 h3 = __float2bfloat16_rn(p3);
                unsigned o0 = sw_off_p(r0, c);
                unsigned o1 = sw_off_p(r1, c);
                *(unsigned*)(smem + SM_PH + o0) = pack2(h0, h1);
                *(unsigned*)(smem + SM_PH + o1) = pack2(h2, h3);
                *(unsigned*)(smem + SM_PL + o0) =
                    pack2(__float2bfloat16_rn(p0 - __bfloat162float(h0)),
                          __float2bfloat16_rn(p1 - __bfloat162float(h1)));
                *(unsigned*)(smem + SM_PL + o1) =
                    pack2(__float2bfloat16_rn(p2 - __bfloat162float(h2)),
                          __float2bfloat16_rn(p3 - __bfloat162float(h3)));
            }
        }
        __syncthreads();   // P ready for both warp halves

        // ---- GEMM2: O[16 x 64] += Ph.Vh + Pl.Vh + Ph.Vl ----
        #pragma unroll
        for (int kc = 0; kc < 4; kc++) {
            unsigned aH[4], aL[4], bb[16];
            unsigned aofs = (((unsigned)(2 * kc) + uAadd) ^ xA) << 4;
            LDSMX4(aH, paH + aofs);
            LDSMX4(aL, paL + aofs);
            #pragma unroll
            for (int np = 0; np < 4; np++) {
                unsigned u = (unsigned)(nh * 8 + np * 2) + uAadd;
                LDSMX4T(&bb[np * 4], vhb + kc * 4096 + ((u ^ xA) << 4));
            }
            #pragma unroll
            for (int nt = 0; nt < 8; nt++) mma16816(O[nt], aH, &bb[nt * 2]);
            #pragma unroll
            for (int nt = 0; nt < 8; nt++) mma16816(O[nt], aL, &bb[nt * 2]);
            #pragma unroll
            for (int np = 0; np < 4; np++) {
                unsigned u = (unsigned)(nh * 8 + np * 2) + uAadd;
                LDSMX4T(&bb[np * 4], vlb + kc * 4096 + ((u ^ xA) << 4));
            }
            #pragma unroll
            for (int nt = 0; nt < 8; nt++) mma16816(O[nt], aH, &bb[nt * 2]);
        }
    }

    // ---- epilogue: row sums across quad + warp pair, normalize, store ----
    __syncthreads();   // all GEMM2 done; P buffer reusable as scratch
    lsum0 += __shfl_xor_sync(0xffffffffu, lsum0, 1);
    lsum0 += __shfl_xor_sync(0xffffffffu, lsum0, 2);
    lsum1 += __shfl_xor_sync(0xffffffffu, lsum1, 1);
    lsum1 += __shfl_xor_sync(0xffffffffu, lsum1, 2);

    const int r0 = lane >> 2;
    if ((lane & 3) == 0) {
        *(float*)(smem + SM_PH + (unsigned)(nh * 64 + wm + r0) * 4) = lsum0;
        *(float*)(smem + SM_PH + (unsigned)(nh * 64 + wm + r0 + 8) * 4) = lsum1;
    }
    __syncthreads();
    float tot0 = lsum0 + *(const float*)(smem + SM_PH + (unsigned)((1 - nh) * 64 + wm + r0) * 4);
    float tot1 = lsum1 + *(const float*)(smem + SM_PH + (unsigned)((1 - nh) * 64 + wm + r0 + 8) * 4);
    const float inv0 = 1.0f / tot0;
    const float inv1 = 1.0f / tot1;

    const int gr = m0 + wm + r0;
    float* ob = out + ((size_t)b * 2048 + gr) * 128;
    #pragma unroll
    for (int nt = 0; nt < 8; nt++) {
        int col = nh * 64 + nt * 8 + (lane & 3) * 2;
        *(float2*)(ob + col) = make_float2(O[nt][0] * inv0, O[nt][1] * inv0);
        *(float2*)(ob + 8 * 128 + col) = make_float2(O[nt][2] * inv1, O[nt][3] * inv1);
    }
}

extern "C" void kernel_launch(void* const* d_in, const int* in_sizes, int n_in,
                              void* d_out, int out_size)
{
    const float* q = (const float*)d_in[0];
    const float* k = (const float*)d_in[1];
    const float* v = (const float*)d_in[2];
    float* out = (float*)d_out;

    cudaFuncSetAttribute(fa_mma2_kernel,
                         cudaFuncAttributeMaxDynamicSharedMemorySize, SM_TOTAL);

    dim3 grid(32, 32);
    fa_mma2_kernel<<<grid, 256, SM_TOTAL>>>(q, k, v, out);
}

// round 12
// speedup vs baseline: 1.8712x; 1.8196x over previous
#include <cuda_runtime.h>
#include <cuda_bf16.h>

// Flash attention: GEMM1 = tf32 mma (K via cp.async, truncated tf32),
// GEMM2 = bf16x3 split (proven). Grid (16, 32), 256 threads = 8 warps.

// log2(e)/sqrt(128), folded exactly at compile time; softmax uses ex2.
#define SCALE_LOG2E (1.4426950408889634f * 0.08838834764831845f)

// ---- SMEM layout (bytes) ----
#define SM_QF 0           // Q fp32(tf32-rn) [128][128], 512B rows swizzled
#define SM_KF 65536       // K fp32 raw, 2 bufs x [64][128] (32768 each)
#define SM_VH 131072      // V hi bf16, 2 bufs x [64][128] (16384 each, 256B rows)
#define SM_VL 163840      // V lo bf16, 2 bufs
#define SM_TOTAL 196608

#define LDSMX4(R, A) \
    asm volatile("ldmatrix.sync.aligned.m8n8.x4.shared.b16 {%0,%1,%2,%3}, [%4];" \
        : "=r"((R)[0]), "=r"((R)[1]), "=r"((R)[2]), "=r"((R)[3]) : "r"(A))

#define LDSMX4T(R, A) \
    asm volatile("ldmatrix.sync.aligned.m8n8.x4.trans.shared.b16 {%0,%1,%2,%3}, [%4];" \
        : "=r"((R)[0]), "=r"((R)[1]), "=r"((R)[2]), "=r"((R)[3]) : "r"(A))

__device__ __forceinline__ void mma16816(float* d, const unsigned* a, const unsigned* b) {
    asm volatile(
        "mma.sync.aligned.m16n8k16.row.col.f32.bf16.bf16.f32 "
        "{%0,%1,%2,%3}, {%4,%5,%6,%7}, {%8,%9}, {%0,%1,%2,%3};"
        : "+f"(d[0]), "+f"(d[1]), "+f"(d[2]), "+f"(d[3])
        : "r"(a[0]), "r"(a[1]), "r"(a[2]), "r"(a[3]), "r"(b[0]), "r"(b[1]));
}

__device__ __forceinline__ void mma1688tf(float* d, const unsigned* a, const unsigned* b) {
    asm volatile(
        "mma.sync.aligned.m16n8k8.row.col.f32.tf32.tf32.f32 "
        "{%0,%1,%2,%3}, {%4,%5,%6,%7}, {%8,%9}, {%0,%1,%2,%3};"
        : "+f"(d[0]), "+f"(d[1]), "+f"(d[2]), "+f"(d[3])
        : "r"(a[0]), "r"(a[1]), "r"(a[2]), "r"(a[3]), "r"(b[0]), "r"(b[1]));
}

__device__ __forceinline__ float ex2f(float x) {
    float r;
    asm("ex2.approx.f32 %0, %1;" : "=f"(r) : "f"(x));
    return r;
}

__device__ __forceinline__ unsigned totf32(float x) {
    unsigned r;
    asm("cvt.rna.tf32.f32 %0, %1;" : "=r"(r) : "f"(x));
    return r;
}

__device__ __forceinline__ unsigned smem_u32(const void* p) {
    unsigned a;
    asm("{ .reg .u64 t; cvta.to.shared.u64 t, %1; cvt.u32.u64 %0, t; }"
        : "=r"(a) : "l"(p));
    return a;
}

__device__ __forceinline__ void cp_async16(unsigned saddr, const void* gaddr) {
    asm volatile("cp.async.cg.shared.global [%0], [%1], 16;"
                 :: "r"(saddr), "l"(gaddr));
}
__device__ __forceinline__ void cp_commit() {
    asm volatile("cp.async.commit_group;");
}
__device__ __forceinline__ void cp_wait0() {
    asm volatile("cp.async.wait_group 0;");
}

__device__ __forceinline__ unsigned pack2(__nv_bfloat16 a, __nv_bfloat16 b) {
    return (unsigned)__bfloat16_as_ushort(a) | ((unsigned)__bfloat16_as_ushort(b) << 16);
}

// swizzled byte offset in a [rows][128 bf16] tile (256B rows, 16B units XOR row&7)
__device__ __forceinline__ unsigned sw_off(int row, int c4) {
    unsigned u = (unsigned)c4 >> 3;
    return (unsigned)row * 256u + ((u ^ ((unsigned)row & 7u)) << 4) +
           (((unsigned)c4 & 4u) << 1);
}

// swizzled byte offset in a [rows][128 fp32] tile (512B rows, 16B units XOR row&7)
__device__ __forceinline__ unsigned sw_off32(int row, int c4) {
    unsigned u = (unsigned)c4 >> 2;
    return (unsigned)row * 512u + ((u ^ ((unsigned)row & 7u)) << 4);
}

__device__ __forceinline__ void split_store(char* hb, char* lb, unsigned off, float4 x) {
    __nv_bfloat16 h0 = __float2bfloat16_rn(x.x);
    __nv_bfloat16 h1 = __float2bfloat16_rn(x.y);
    __nv_bfloat16 h2 = __float2bfloat16_rn(x.z);
    __nv_bfloat16 h3 = __float2bfloat16_rn(x.w);
    __nv_bfloat16 l0 = __float2bfloat16_rn(x.x - __bfloat162float(h0));
    __nv_bfloat16 l1 = __float2bfloat16_rn(x.y - __bfloat162float(h1));
    __nv_bfloat16 l2 = __float2bfloat16_rn(x.z - __bfloat162float(h2));
    __nv_bfloat16 l3 = __float2bfloat16_rn(x.w - __bfloat162float(h3));
    *(uint2*)(hb + off) = make_uint2(pack2(h0, h1), pack2(h2, h3));
    *(uint2*)(lb + off) = make_uint2(pack2(l0, l1), pack2(l2, l3));
}

// K tile (64x128 fp32) via cp.async: 8 x 16B per thread, swizzled destination
__device__ __forceinline__ void cpasync_k(unsigned kdst, const float* kb, int tid) {
    #pragma unroll
    for (int j = 0; j < 8; j++) {
        int lin = j * 256 + tid;
        int row = lin >> 5;
        int c4  = (lin & 31) << 2;
        cp_async16(kdst + sw_off32(row, c4), kb + row * 128 + c4);
    }
    cp_commit();
}

// one 64x128 fp32 tile: 2048 float4, 8 per thread (batched for MLP)
__device__ __forceinline__ void ldg8(const float* base, int tid, float4* r) {
    #pragma unroll
    for (int j = 0; j < 8; j++) {
        int lin = j * 256 + tid;
        int row = lin >> 5;
        int c4  = (lin & 31) << 2;
        r[j] = *(const float4*)(base + row * 128 + c4);
    }
}

// store V tile: bf16 hi/lo split
__device__ __forceinline__ void sts8v(char* hb, char* lb, int tid, const float4* r) {
    #pragma unroll
    for (int j = 0; j < 8; j++) {
        int lin = j * 256 + tid;
        int row = lin >> 5;
        int c4  = (lin & 31) << 2;
        split_store(hb, lb, sw_off(row, c4), r[j]);
    }
}

__global__ void __launch_bounds__(256, 1)
fa_tf32_kernel(const float* __restrict__ q, const float* __restrict__ k,
               const float* __restrict__ v, float* __restrict__ out)
{
    extern __shared__ __align__(1024) char smem[];
    const unsigned sb = smem_u32(smem);
    const int tid  = threadIdx.x;
    const int wid  = tid >> 5;
    const int lane = tid & 31;
    const int b    = blockIdx.y;
    const int m0   = blockIdx.x * 128;
    const int wm   = wid * 16;

    // lane decompositions for ldmatrix addressing
    const int lrowA = lane & 15;
    const unsigned xA = (unsigned)(lane & 7);
    const int lnB  = ((lane >> 4) << 3) + (lane & 7);
    const unsigned uAadd = (unsigned)(lane >> 4);
    const unsigned uBadd = (unsigned)((lane & 8) >> 3);

    const float* kbase = k + (size_t)b * 2048 * 128;
    const float* vbase = v + (size_t)b * 2048 * 128;

    // ---- prologue: start K(0) copy, then Q (scale+rn-tf32), then V(0) ----
    cpasync_k(sb + SM_KF, kbase, tid);

    const float* qb = q + ((size_t)b * 2048 + m0) * 128;
    {
        char* QF = smem + SM_QF;
        #pragma unroll
        for (int j = 0; j < 16; j++) {
            int lin = j * 256 + tid;
            int row = lin >> 5;
            int c4  = (lin & 31) << 2;
            float4 x = *(const float4*)(qb + row * 128 + c4);
            uint4 t = make_uint4(totf32(x.x * SCALE_LOG2E), totf32(x.y * SCALE_LOG2E),
                                 totf32(x.z * SCALE_LOG2E), totf32(x.w * SCALE_LOG2E));
            *(uint4*)(QF + sw_off32(row, c4)) = t;
        }
    }
    {
        float4 r[8];
        ldg8(vbase, tid, r);
        sts8v(smem + SM_VH, smem + SM_VL, tid, r);
    }
    cp_wait0();
    __syncthreads();

    float O[16][4];
    #pragma unroll
    for (int i = 0; i < 16; i++)
        #pragma unroll
        for (int j = 0; j < 4; j++) O[i][j] = 0.0f;
    float lsum0 = 0.0f, lsum1 = 0.0f;

    const unsigned qaF = sb + SM_QF + (unsigned)(wm + lrowA) * 512;

    for (int t = 0; t < 32; t++) {
        const int buf = t & 1;
        const int nbuf = buf ^ 1;

        // ---- background-copy K(t+1) into nbuf (no registers held) ----
        if (t < 31)
            cpasync_k(sb + SM_KF + nbuf * 32768, kbase + (size_t)(t + 1) * 8192, tid);

        // ---- GEMM1 (tf32): S[16 x 64] = Q . K^T ----
        float S[8][4];
        #pragma unroll
        for (int nt = 0; nt < 8; nt++)
            #pragma unroll
            for (int j = 0; j < 4; j++) S[nt][j] = 0.0f;

        const unsigned khb = sb + SM_KF + buf * 32768 + (unsigned)lnB * 512;

        #pragma unroll
        for (int ks = 0; ks < 16; ks++) {
            unsigned a[4], bb[16];
            unsigned aofs = (((unsigned)(2 * ks) + uAadd) ^ xA) << 4;
            LDSMX4(a, qaF + aofs);
            unsigned bofs = (((unsigned)(2 * ks) + uBadd) ^ xA) << 4;
            #pragma unroll
            for (int np = 0; np < 4; np++)
                LDSMX4(&bb[np * 4], khb + np * 8192 + bofs);   // 16 rows x 512B
            #pragma unroll
            for (int nt = 0; nt < 8; nt++) mma1688tf(S[nt], a, &bb[nt * 2]);
        }

        // ---- softmax: p = 2^s; split to bf16 hi/lo in registers ----
        unsigned Ph[16], Pl[16];
        #pragma unroll
        for (int nt = 0; nt < 8; nt++) {
            float p0 = ex2f(S[nt][0]);
            float p1 = ex2f(S[nt][1]);
            float p2 = ex2f(S[nt][2]);
            float p3 = ex2f(S[nt][3]);
            lsum0 += p0 + p1;
            lsum1 += p2 + p3;
            __nv_bfloat16 h0 = __float2bfloat16_rn(p0);
            __nv_bfloat16 h1 = __float2bfloat16_rn(p1);
            __nv_bfloat16 h2 = __float2bfloat16_rn(p2);
            __nv_bfloat16 h3 = __float2bfloat16_rn(p3);
            Ph[nt * 2]     = pack2(h0, h1);
            Ph[nt * 2 + 1] = pack2(h2, h3);
            Pl[nt * 2]     = pack2(__float2bfloat16_rn(p0 - __bfloat162float(h0)),
                                   __float2bfloat16_rn(p1 - __bfloat162float(h1)));
            Pl[nt * 2 + 1] = pack2(__float2bfloat16_rn(p2 - __bfloat162float(h2)),
                                   __float2bfloat16_rn(p3 - __bfloat162float(h3)));
        }

        // ---- issue V(t+1) loads (covered by GEMM2) ----
        float4 vpre[8];
        if (t < 31) ldg8(vbase + (size_t)(t + 1) * 8192, tid, vpre);

        // ---- GEMM2 (bf16x3): O += Ph.Vh + Pl.Vh + Ph.Vl ----
        const unsigned vhb = sb + SM_VH + buf * 16384 + (unsigned)lrowA * 256;
        const unsigned vlb = vhb + 32768;
        #pragma unroll
        for (int ks2 = 0; ks2 < 4; ks2++) {
            const unsigned* Ah = &Ph[ks2 * 4];
            const unsigned* Al = &Pl[ks2 * 4];
            #pragma unroll
            for (int g = 0; g < 2; g++) {
                unsigned bb[16];
                #pragma unroll
                for (int np = 0; np < 4; np++) {
                    unsigned u = (unsigned)(g * 8 + np * 2) + uAadd;
                    LDSMX4T(&bb[np * 4], vhb + ks2 * 4096 + ((u ^ xA) << 4));
                }
                #pragma unroll
                for (int nt = 0; nt < 8; nt++) mma16816(O[g * 8 + nt], Ah, &bb[nt * 2]);
                #pragma unroll
                for (int nt = 0; nt < 8; nt++) mma16816(O[g * 8 + nt], Al, &bb[nt * 2]);
                #pragma unroll
                for (int np = 0; np < 4; np++) {
                    unsigned u = (unsigned)(g * 8 + np * 2) + uAadd;
                    LDSMX4T(&bb[np * 4], vlb + ks2 * 4096 + ((u ^ xA) << 4));
                }
                #pragma unroll
                for (int nt = 0; nt < 8; nt++) mma16816(O[g * 8 + nt], Ah, &bb[nt * 2]);
            }
        }

        // ---- store V(t+1); drain K(t+1) cp.async ----
        if (t < 31)
            sts8v(smem + SM_VH + nbuf * 16384, smem + SM_VL + nbuf * 16384, tid, vpre);
        cp_wait0();
        __syncthreads();
    }

    // ---- epilogue: quad-reduce row sums, normalize, store ----
    lsum0 += __shfl_xor_sync(0xffffffffu, lsum0, 1);
    lsum0 += __shfl_xor_sync(0xffffffffu, lsum0, 2);
    lsum1 += __shfl_xor_sync(0xffffffffu, lsum1, 1);
    lsum1 += __shfl_xor_sync(0xffffffffu, lsum1, 2);
    const float inv0 = 1.0f / lsum0;
    const float inv1 = 1.0f / lsum1;

    const int r0 = m0 + wm + (lane >> 2);
    float* ob = out + ((size_t)b * 2048 + r0) * 128;
    #pragma unroll
    for (int nt = 0; nt < 16; nt++) {
        int col = nt * 8 + (lane & 3) * 2;
        *(float2*)(ob + col) = make_float2(O[nt][0] * inv0, O[nt][1] * inv0);
        *(float2*)(ob + 8 * 128 + col) = make_float2(O[nt][2] * inv1, O[nt][3] * inv1);
    }
}

extern "C" void kernel_launch(void* const* d_in, const int* in_sizes, int n_in,
                              void* d_out, int out_size)
{
    const float* q = (const float*)d_in[0];
    const float* k = (const float*)d_in[1];
    const float* v = (const float*)d_in[2];
    float* out = (float*)d_out;

    cudaFuncSetAttribute(fa_tf32_kernel,
                         cudaFuncAttributeMaxDynamicSharedMemorySize, SM_TOTAL);

    dim3 grid(16, 32);
    fa_tf32_kernel<<<grid, 256, SM_TOTAL>>>(q, k, v, out);
}

// round 13
// speedup vs baseline: 3.3307x; 1.7800x over previous
#include <cuda_runtime.h>
#include <cuda_bf16.h>

// Flash attention: GEMM1 = tf32 mma (K via cp.async raw, bias-compensated),
// GEMM2 = single-pass fp16 mma. Grid (16, 32), 256 threads = 8 warps.

// log2(e)/sqrt(128) * (1 + 3.38e-4): the last factor cancels the mean
// mantissa-truncation bias of raw-fp32 K consumed as tf32.
#define SCALE_LOG2E (1.4426950408889634f * 0.08838834764831845f * 1.000338f)

// ---- SMEM layout (bytes) ----
#define SM_QF 0           // Q fp32(tf32-rn) [128][128], 512B rows swizzled
#define SM_KF 65536       // K fp32 raw, 2 bufs x [64][128] (32768 each)
#define SM_VH 131072      // V fp16, 2 bufs x [64][128] (16384 each, 256B rows)
#define SM_TOTAL 163840

#define LDSMX4(R, A) \
    asm volatile("ldmatrix.sync.aligned.m8n8.x4.shared.b16 {%0,%1,%2,%3}, [%4];" \
        : "=r"((R)[0]), "=r"((R)[1]), "=r"((R)[2]), "=r"((R)[3]) : "r"(A))

#define LDSMX4T(R, A) \
    asm volatile("ldmatrix.sync.aligned.m8n8.x4.trans.shared.b16 {%0,%1,%2,%3}, [%4];" \
        : "=r"((R)[0]), "=r"((R)[1]), "=r"((R)[2]), "=r"((R)[3]) : "r"(A))

__device__ __forceinline__ void mma16816h(float* d, const unsigned* a, const unsigned* b) {
    asm volatile(
        "mma.sync.aligned.m16n8k16.row.col.f32.f16.f16.f32 "
        "{%0,%1,%2,%3}, {%4,%5,%6,%7}, {%8,%9}, {%0,%1,%2,%3};"
        : "+f"(d[0]), "+f"(d[1]), "+f"(d[2]), "+f"(d[3])
        : "r"(a[0]), "r"(a[1]), "r"(a[2]), "r"(a[3]), "r"(b[0]), "r"(b[1]));
}

__device__ __forceinline__ void mma1688tf(float* d, const unsigned* a, const unsigned* b) {
    asm volatile(
        "mma.sync.aligned.m16n8k8.row.col.f32.tf32.tf32.f32 "
        "{%0,%1,%2,%3}, {%4,%5,%6,%7}, {%8,%9}, {%0,%1,%2,%3};"
        : "+f"(d[0]), "+f"(d[1]), "+f"(d[2]), "+f"(d[3])
        : "r"(a[0]), "r"(a[1]), "r"(a[2]), "r"(a[3]), "r"(b[0]), "r"(b[1]));
}

__device__ __forceinline__ float ex2f(float x) {
    float r;
    asm("ex2.approx.f32 %0, %1;" : "=f"(r) : "f"(x));
    return r;
}

__device__ __forceinline__ unsigned totf32(float x) {
    unsigned r;
    asm("cvt.rna.tf32.f32 %0, %1;" : "=r"(r) : "f"(x));
    return r;
}

// pack two floats into f16x2: hi half = 'hi', lo half = 'lo'
__device__ __forceinline__ unsigned pack_f16x2(float hi, float lo) {
    unsigned d;
    asm("cvt.rn.f16x2.f32 %0, %1, %2;" : "=r"(d) : "f"(hi), "f"(lo));
    return d;
}

__device__ __forceinline__ unsigned smem_u32(const void* p) {
    unsigned a;
    asm("{ .reg .u64 t; cvta.to.shared.u64 t, %1; cvt.u32.u64 %0, t; }"
        : "=r"(a) : "l"(p));
    return a;
}

__device__ __forceinline__ void cp_async16(unsigned saddr, const void* gaddr) {
    asm volatile("cp.async.cg.shared.global [%0], [%1], 16;"
                 :: "r"(saddr), "l"(gaddr));
}
__device__ __forceinline__ void cp_commit() {
    asm volatile("cp.async.commit_group;");
}
__device__ __forceinline__ void cp_wait0() {
    asm volatile("cp.async.wait_group 0;");
}

// swizzled byte offset in a [rows][128 x 16-bit] tile (256B rows, 16B units XOR row&7)
__device__ __forceinline__ unsigned sw_off(int row, int c4) {
    unsigned u = (unsigned)c4 >> 3;
    return (unsigned)row * 256u + ((u ^ ((unsigned)row & 7u)) << 4) +
           (((unsigned)c4 & 4u) << 1);
}

// swizzled byte offset in a [rows][128 fp32] tile (512B rows, 16B units XOR row&7)
__device__ __forceinline__ unsigned sw_off32(int row, int c4) {
    unsigned u = (unsigned)c4 >> 2;
    return (unsigned)row * 512u + ((u ^ ((unsigned)row & 7u)) << 4);
}

// K tile (64x128 fp32) via cp.async: 8 x 16B per thread, swizzled destination
__device__ __forceinline__ void cpasync_k(unsigned kdst, const float* kb, int tid) {
    #pragma unroll
    for (int j = 0; j < 8; j++) {
        int lin = j * 256 + tid;
        int row = lin >> 5;
        int c4  = (lin & 31) << 2;
        cp_async16(kdst + sw_off32(row, c4), kb + row * 128 + c4);
    }
    cp_commit();
}

// one 64x128 fp32 tile: 2048 float4, 8 per thread (batched for MLP)
__device__ __forceinline__ void ldg8(const float* base, int tid, float4* r) {
    #pragma unroll
    for (int j = 0; j < 8; j++) {
        int lin = j * 256 + tid;
        int row = lin >> 5;
        int c4  = (lin & 31) << 2;
        r[j] = *(const float4*)(base + row * 128 + c4);
    }
}

// store V tile as fp16 (single precision level)
__device__ __forceinline__ void sts8vh(char* hb, int tid, const float4* r) {
    #pragma unroll
    for (int j = 0; j < 8; j++) {
        int lin = j * 256 + tid;
        int row = lin >> 5;
        int c4  = (lin & 31) << 2;
        *(uint2*)(hb + sw_off(row, c4)) =
            make_uint2(pack_f16x2(r[j].y, r[j].x), pack_f16x2(r[j].w, r[j].z));
    }
}

__global__ void __launch_bounds__(256, 1)
fa_tf32h_kernel(const float* __restrict__ q, const float* __restrict__ k,
                const float* __restrict__ v, float* __restrict__ out)
{
    extern __shared__ __align__(1024) char smem[];
    const unsigned sb = smem_u32(smem);
    const int tid  = threadIdx.x;
    const int wid  = tid >> 5;
    const int lane = tid & 31;
    const int b    = blockIdx.y;
    const int m0   = blockIdx.x * 128;
    const int wm   = wid * 16;

    // lane decompositions for ldmatrix addressing
    const int lrowA = lane & 15;
    const unsigned xA = (unsigned)(lane & 7);
    const int lnB  = ((lane >> 4) << 3) + (lane & 7);
    const unsigned uAadd = (unsigned)(lane >> 4);
    const unsigned uBadd = (unsigned)((lane & 8) >> 3);

    const float* kbase = k + (size_t)b * 2048 * 128;
    const float* vbase = v + (size_t)b * 2048 * 128;

    // ---- prologue: start K(0) copy, then Q (scale+rn-tf32), then V(0) ----
    cpasync_k(sb + SM_KF, kbase, tid);

    const float* qb = q + ((size_t)b * 2048 + m0) * 128;
    {
        char* QF = smem + SM_QF;
        #pragma unroll
        for (int j = 0; j < 16; j++) {
            int lin = j * 256 + tid;
            int row = lin >> 5;
            int c4  = (lin & 31) << 2;
            float4 x = *(const float4*)(qb + row * 128 + c4);
            uint4 t = make_uint4(totf32(x.x * SCALE_LOG2E), totf32(x.y * SCALE_LOG2E),
                                 totf32(x.z * SCALE_LOG2E), totf32(x.w * SCALE_LOG2E));
            *(uint4*)(QF + sw_off32(row, c4)) = t;
        }
    }
    {
        float4 r[8];
        ldg8(vbase, tid, r);
        sts8vh(smem + SM_VH, tid, r);
    }
    cp_wait0();
    __syncthreads();

    float O[16][4];
    #pragma unroll
    for (int i = 0; i < 16; i++)
        #pragma unroll
        for (int j = 0; j < 4; j++) O[i][j] = 0.0f;
    float lsum0 = 0.0f, lsum1 = 0.0f;

    const unsigned qaF = sb + SM_QF + (unsigned)(wm + lrowA) * 512;

    for (int t = 0; t < 32; t++) {
        const int buf = t & 1;
        const int nbuf = buf ^ 1;

        // ---- background-copy K(t+1) into nbuf (no registers held) ----
        if (t < 31)
            cpasync_k(sb + SM_KF + nbuf * 32768, kbase + (size_t)(t + 1) * 8192, tid);

        // ---- GEMM1 (tf32): S[16 x 64] = Q . K^T ----
        float S[8][4];
        #pragma unroll
        for (int nt = 0; nt < 8; nt++)
            #pragma unroll
            for (int j = 0; j < 4; j++) S[nt][j] = 0.0f;

        const unsigned khb = sb + SM_KF + buf * 32768 + (unsigned)lnB * 512;

        #pragma unroll
        for (int ks = 0; ks < 16; ks++) {
            unsigned a[4], bb[16];
            unsigned aofs = (((unsigned)(2 * ks) + uAadd) ^ xA) << 4;
            LDSMX4(a, qaF + aofs);
            unsigned bofs = (((unsigned)(2 * ks) + uBadd) ^ xA) << 4;
            #pragma unroll
            for (int np = 0; np < 4; np++)
                LDSMX4(&bb[np * 4], khb + np * 8192 + bofs);   // 16 rows x 512B
            #pragma unroll
            for (int nt = 0; nt < 8; nt++) mma1688tf(S[nt], a, &bb[nt * 2]);
        }

        // ---- issue V(t+1) loads (covered by softmax + GEMM2) ----
        float4 vpre[8];
        if (t < 31) ldg8(vbase + (size_t)(t + 1) * 8192, tid, vpre);

        // ---- softmax: p = 2^s; pack to f16x2 in registers ----
        // C-frag layout == f16 k16 A-frag layout for GEMM2.
        unsigned Ph[16];
        #pragma unroll
        for (int nt = 0; nt < 8; nt++) {
            float p0 = ex2f(S[nt][0]);
            float p1 = ex2f(S[nt][1]);
            float p2 = ex2f(S[nt][2]);
            float p3 = ex2f(S[nt][3]);
            lsum0 += p0 + p1;
            lsum1 += p2 + p3;
            Ph[nt * 2]     = pack_f16x2(p1, p0);
            Ph[nt * 2 + 1] = pack_f16x2(p3, p2);
        }

        // ---- GEMM2 (fp16 single pass): O += P . V ----
        const unsigned vhb = sb + SM_VH + buf * 16384 + (unsigned)lrowA * 256;
        #pragma unroll
        for (int ks2 = 0; ks2 < 4; ks2++) {
            const unsigned* Ah = &Ph[ks2 * 4];
            #pragma unroll
            for (int g = 0; g < 2; g++) {
                unsigned bb[16];
                #pragma unroll
                for (int np = 0; np < 4; np++) {
                    unsigned u = (unsigned)(g * 8 + np * 2) + uAadd;
                    LDSMX4T(&bb[np * 4], vhb + ks2 * 4096 + ((u ^ xA) << 4));
                }
                #pragma unroll
                for (int nt = 0; nt < 8; nt++) mma16816h(O[g * 8 + nt], Ah, &bb[nt * 2]);
            }
        }

        // ---- store V(t+1) fp16; drain K(t+1) cp.async ----
        if (t < 31)
            sts8vh(smem + SM_VH + nbuf * 16384, tid, vpre);
        cp_wait0();
        __syncthreads();
    }

    // ---- epilogue: quad-reduce row sums, normalize, store ----
    lsum0 += __shfl_xor_sync(0xffffffffu, lsum0, 1);
    lsum0 += __shfl_xor_sync(0xffffffffu, lsum0, 2);
    lsum1 += __shfl_xor_sync(0xffffffffu, lsum1, 1);
    lsum1 += __shfl_xor_sync(0xffffffffu, lsum1, 2);
    const float inv0 = 1.0f / lsum0;
    const float inv1 = 1.0f / lsum1;

    const int r0 = m0 + wm + (lane >> 2);
    float* ob = out + ((size_t)b * 2048 + r0) * 128;
    #pragma unroll
    for (int nt = 0; nt < 16; nt++) {
        int col = nt * 8 + (lane & 3) * 2;
        *(float2*)(ob + col) = make_float2(O[nt][0] * inv0, O[nt][1] * inv0);
        *(float2*)(ob + 8 * 128 + col) = make_float2(O[nt][2] * inv1, O[nt][3] * inv1);
    }
}

extern "C" void kernel_launch(void* const* d_in, const int* in_sizes, int n_in,
                              void* d_out, int out_size)
{
    const float* q = (const float*)d_in[0];
    const float* k = (const float*)d_in[1];
    const float* v = (const float*)d_in[2];
    float* out = (float*)d_out;

    cudaFuncSetAttribute(fa_tf32h_kernel,
                         cudaFuncAttributeMaxDynamicSharedMemorySize, SM_TOTAL);

    dim3 grid(16, 32);
    fa_tf32h_kernel<<<grid, 256, SM_TOTAL>>>(q, k, v, out);
}